// round 10
// baseline (speedup 1.0000x reference)
#include <cuda_runtime.h>
#include <cuda_fp16.h>
#include <cstdint>

typedef unsigned long long ull;

constexpr int NN = 100000;   // nodes
constexpr int EE = 1600000;  // edges (no self loops)
constexpr int NB = 196;      // build-kernel blocks (co-resident, 1.33/SM)
constexpr int CHUNK = 512;   // nodes per build block (2 per thread)

struct __align__(8) Edge { int s; float w; };

// ---------------- static device scratch --------------------------------------
__device__ int      g_is64;
__device__ int      g_cnt[NN];
__device__ int      g_rowptr[NN + 1];
__device__ int      g_bsum[256];
__device__ float    g_dinv[NN];
__device__ Edge     g_edge[EE];
__device__ float    g_buf2[(size_t)NN * 128];
__device__ __half   g_hbuf[(size_t)NN * 96];
__device__ unsigned g_bcnt[8];    // grid-barrier arrive counters (self-reset)
__device__ unsigned g_bsense[8];  // grid-barrier senses (monotonic)

__device__ __forceinline__ const float* sel_src(const float* ext, int s) {
    return s == 0 ? ext : (const float*)g_buf2;
}
__device__ __forceinline__ float* sel_dst(float* ext, int s) {
    return s == 0 ? ext : (float*)g_buf2;
}

// tf32 helpers (arch-agnostic PTX, sm_80+)
__device__ __forceinline__ uint32_t f2tf32(float f) {
    uint32_t r;
    asm("cvt.rna.tf32.f32 %0, %1;" : "=r"(r) : "f"(f));
    return r;
}
__device__ __forceinline__ void mma_tf32_16n8k8(float* c, const uint32_t* a,
                                                const uint32_t* b) {
    asm volatile(
        "mma.sync.aligned.m16n8k8.row.col.f32.tf32.tf32.f32 "
        "{%0,%1,%2,%3}, {%4,%5,%6,%7}, {%8,%9}, {%0,%1,%2,%3};"
        : "+f"(c[0]), "+f"(c[1]), "+f"(c[2]), "+f"(c[3])
        : "r"(a[0]), "r"(a[1]), "r"(a[2]), "r"(a[3]), "r"(b[0]), "r"(b[1]));
}

// load 8 halfs (16B) -> 8 floats
__device__ __forceinline__ void ld_half8(const __half* p, float* f) {
    uint4 r = *(const uint4*)p;
    const __half2* h2 = (const __half2*)&r;
#pragma unroll
    for (int j = 0; j < 4; j++) {
        float2 t = __half22float2(h2[j]);
        f[2 * j] = t.x; f[2 * j + 1] = t.y;
    }
}

__device__ __forceinline__ int load_idx(const int* __restrict__ w, int pos, int is64) {
    if (is64) return ((const int2*)w)[pos].x;
    return w[pos];
}

// ---------------- software grid barrier (all NB blocks resident) -------------
__device__ __forceinline__ void gbar(int slot, int nb) {
    __syncthreads();
    if (threadIdx.x == 0) {
        __threadfence();
        unsigned s = atomicAdd(&g_bsense[slot], 0u);  // read BEFORE arriving
        if (atomicAdd(&g_bcnt[slot], 1u) == (unsigned)nb - 1u) {
            g_bcnt[slot] = 0;
            __threadfence();
            atomicAdd(&g_bsense[slot], 1u);           // release
        } else {
            while (atomicAdd(&g_bsense[slot], 0u) == s) __nanosleep(64);
        }
    }
    __syncthreads();
}

// ---------------- fused CSR build: detect/count/dinv/scan/scatter ------------
__global__ __launch_bounds__(256) void k_build(const int* __restrict__ w, int E) {
    int b = blockIdx.x, t = threadIdx.x;
    int gid = b * 256 + t;
    const int nthr = NB * 256;
    __shared__ int sh[256];

    // phase 0: zero counts + dtype detect
    for (int i = gid; i < NN; i += nthr) g_cnt[i] = 0;
    if (b == 0 && t < 32) {
        int acc = 0;
        for (int j = t; j < 1024; j += 32) acc |= w[2 * j + 1];
#pragma unroll
        for (int off = 16; off > 0; off >>= 1)
            acc |= __shfl_xor_sync(0xffffffffu, acc, off);
        if (t == 0) g_is64 = (acc == 0) ? 1 : 0;
    }
    gbar(0, NB);
    int is64 = g_is64;

    // phase 1: degree count
    for (int e = gid; e < E; e += nthr) {
        int d = load_idx(w, E + e, is64);
        if ((unsigned)d < (unsigned)NN) atomicAdd(&g_cnt[d], 1);
    }
    gbar(1, NB);

    // phase 2a: per-thread sums of 2 nodes, dinv, block total
    int n0 = b * CHUNK + t * 2;
    int c0 = 0, c1 = 0;
    if (n0 < NN)     { int c = g_cnt[n0];     c0 = c; g_dinv[n0]     = rsqrtf((float)(c + 1)); }
    if (n0 + 1 < NN) { int c = g_cnt[n0 + 1]; c1 = c; g_dinv[n0 + 1] = rsqrtf((float)(c + 1)); }
    int tsum = c0 + c1;
    sh[t] = tsum;
    __syncthreads();
    for (int off = 128; off > 0; off >>= 1) {
        if (t < off) sh[t] += sh[t + off];
        __syncthreads();
    }
    if (t == 0) g_bsum[b] = sh[0];
    gbar(2, NB);

    // phase 2b: block 0 exclusive-scans block sums
    if (b == 0) {
        int v = (t < NB) ? g_bsum[t] : 0;
        sh[t] = v;
        __syncthreads();
        for (int off = 1; off < 256; off <<= 1) {
            int tmp = (t >= off) ? sh[t - off] : 0;
            __syncthreads();
            sh[t] += tmp;
            __syncthreads();
        }
        if (t < NB) g_bsum[t] = sh[t] - v;
        if (t == 255) g_rowptr[NN] = sh[255];
    }
    gbar(3, NB);

    // phase 2c: block-local exclusive scan of thread sums -> rowptr + cursor
    sh[t] = tsum;
    __syncthreads();
    for (int off = 1; off < 256; off <<= 1) {
        int tmp = (t >= off) ? sh[t - off] : 0;
        __syncthreads();
        sh[t] += tmp;
        __syncthreads();
    }
    int off = g_bsum[b] + sh[t] - tsum;
    if (n0 < NN)     { g_rowptr[n0] = off;     g_cnt[n0] = off;     off += c0; }
    if (n0 + 1 < NN) { g_rowptr[n0 + 1] = off; g_cnt[n0 + 1] = off; }
    gbar(4, NB);

    // phase 3: scatter edges
    for (int e = gid; e < E; e += nthr) {
        int s = load_idx(w, e, is64);
        int d = load_idx(w, E + e, is64);
        if ((unsigned)s < (unsigned)NN && (unsigned)d < (unsigned)NN) {
            int pos = atomicAdd(&g_cnt[d], 1);
            Edge ed; ed.s = s; ed.w = g_dinv[s] * g_dinv[d];
            g_edge[pos] = ed;
        }
    }
}

// ---------------- fused layer 1: agg12(x) -> scalar GEMM 12->64 -> fp16 ------
__global__ __launch_bounds__(128) void k_aggemm1(const float* __restrict__ x,
                                                 const float* __restrict__ W,
                                                 const float* __restrict__ bias) {
    constexpr int IN = 12, OUT = 64, BN = 32, HS = 36;
    __shared__ float Wsm[IN * OUT];
    __shared__ float Hsm[IN * HS];
    int tid = threadIdx.x;
    int n0blk = blockIdx.x * BN;

    // stage W (768 floats)
    for (int i = tid; i < IN * OUT; i += 128) Wsm[i] = W[i];

    // agg phase: 4 lanes per node (q=0..2 active, 4 ch each)
    {
        int nr = tid >> 2;          // 0..31
        int q = tid & 3;
        int node = n0blk + nr;
        bool act = (q < 3) && (node < NN);
        int c0 = q * 4;
        float acc[4] = {0.f, 0.f, 0.f, 0.f};
        if (node < NN) {
            float sd = g_dinv[node];
            sd *= sd;
            if (act) {
                float4 v = *(const float4*)&x[(size_t)node * IN + c0];
                acc[0] = sd * v.x; acc[1] = sd * v.y;
                acc[2] = sd * v.z; acc[3] = sd * v.w;
            }
            int e = g_rowptr[node];
            const int end = g_rowptr[node + 1];
            for (; e + 2 <= end; e += 2) {
                Edge e0 = g_edge[e];
                Edge e1 = g_edge[e + 1];
                if (act) {
                    float4 a = *(const float4*)&x[(size_t)e0.s * IN + c0];
                    float4 b4 = *(const float4*)&x[(size_t)e1.s * IN + c0];
                    acc[0] += e0.w * a.x + e1.w * b4.x;
                    acc[1] += e0.w * a.y + e1.w * b4.y;
                    acc[2] += e0.w * a.z + e1.w * b4.z;
                    acc[3] += e0.w * a.w + e1.w * b4.w;
                }
            }
            if (e < end) {
                Edge e0 = g_edge[e];
                if (act) {
                    float4 a = *(const float4*)&x[(size_t)e0.s * IN + c0];
                    acc[0] += e0.w * a.x; acc[1] += e0.w * a.y;
                    acc[2] += e0.w * a.z; acc[3] += e0.w * a.w;
                }
            }
        }
        if (q < 3) {
#pragma unroll
            for (int j = 0; j < 4; j++) Hsm[(c0 + j) * HS + nr] = acc[j];
        }
    }
    __syncthreads();

    // GEMM phase: 16x8 threads, 4x4 per thread
    int tx = tid & 15, ty = tid >> 4;
    int c0g = tx * 4, n0g = ty * 4;
    float acc[4][4];
#pragma unroll
    for (int a = 0; a < 4; a++)
#pragma unroll
        for (int c = 0; c < 4; c++) acc[a][c] = 0.f;
#pragma unroll
    for (int k = 0; k < IN; k++) {
        float4 hv4 = *(const float4*)&Hsm[k * HS + n0g];
        float4 wv4 = *(const float4*)&Wsm[k * OUT + c0g];
        float hv[4] = {hv4.x, hv4.y, hv4.z, hv4.w};
        float wv[4] = {wv4.x, wv4.y, wv4.z, wv4.w};
#pragma unroll
        for (int a = 0; a < 4; a++)
#pragma unroll
            for (int c = 0; c < 4; c++) acc[a][c] += hv[a] * wv[c];
    }
    float4 b4 = *(const float4*)&bias[c0g];
#pragma unroll
    for (int a = 0; a < 4; a++) {
        int node = n0blk + n0g + a;
        if (node < NN) {
            float t0 = fmaxf(acc[a][0] + b4.x, 0.f);
            float t1 = fmaxf(acc[a][1] + b4.y, 0.f);
            float t2 = fmaxf(acc[a][2] + b4.z, 0.f);
            float t3 = fmaxf(acc[a][3] + b4.w, 0.f);
            *(__half2*)&g_hbuf[(size_t)node * OUT + c0g] = __floats2half2_rn(t0, t1);
            *(__half2*)&g_hbuf[(size_t)node * OUT + c0g + 2] = __floats2half2_rn(t2, t3);
        }
    }
}

// ---------------- fused layer 2: agg64(fp16) -> tf32 MMA 64->128 -------------
__global__ __launch_bounds__(256) void k_aggemm2(const float* __restrict__ W,
                                                 const float* __restrict__ bias) {
    constexpr int K = 64, OUT = 128;
    constexpr int AS = 68;        // banks (4g+t4) unique -> conflict-free
    constexpr int KCB = 16;       // B chunk
    constexpr int BS = OUT + 8;   // 136
    constexpr int NT = OUT / 8;   // 16
    __shared__ uint32_t Asm[128 * AS];   // 34.8KB
    __shared__ uint32_t Bsm[KCB * BS];   // 8.7KB

    int tid = threadIdx.x;
    int wid = tid >> 5, lane = tid & 31;
    int g = lane >> 2, t4 = lane & 3;
    int tile0 = blockIdx.x * 128;

    // --- agg phase: GRP=8, VEC=8, fp16 gather from g_hbuf -> tf32 into Asm ---
    {
        int sub = tid & 7;           // 8 lanes/node
        int grp = tid >> 3;          // 32 groups
        int c0 = sub * 8;
        const __half* hh = (const __half*)g_hbuf;
#pragma unroll
        for (int it = 0; it < 4; it++) {
            int row = it * 32 + grp;
            int node = tile0 + row;
            float acc[8];
#pragma unroll
            for (int v = 0; v < 8; v++) acc[v] = 0.f;
            if (node < NN) {
                float sd = g_dinv[node];
                sd *= sd;
                float f[8];
                ld_half8(hh + (size_t)node * K + c0, f);
#pragma unroll
                for (int v = 0; v < 8; v++) acc[v] = sd * f[v];
                int e = g_rowptr[node];
                const int end = g_rowptr[node + 1];
                for (; e + 2 <= end; e += 2) {
                    Edge e0 = g_edge[e];
                    Edge e1 = g_edge[e + 1];
                    float f0[8], f1[8];
                    ld_half8(hh + (size_t)e0.s * K + c0, f0);
                    ld_half8(hh + (size_t)e1.s * K + c0, f1);
#pragma unroll
                    for (int v = 0; v < 8; v++)
                        acc[v] += e0.w * f0[v] + e1.w * f1[v];
                }
                if (e < end) {
                    Edge e0 = g_edge[e];
                    float f0[8];
                    ld_half8(hh + (size_t)e0.s * K + c0, f0);
#pragma unroll
                    for (int v = 0; v < 8; v++) acc[v] += e0.w * f0[v];
                }
            }
            uint4 p0, p1;
            p0.x = f2tf32(acc[0]); p0.y = f2tf32(acc[1]);
            p0.z = f2tf32(acc[2]); p0.w = f2tf32(acc[3]);
            p1.x = f2tf32(acc[4]); p1.y = f2tf32(acc[5]);
            p1.z = f2tf32(acc[6]); p1.w = f2tf32(acc[7]);
            *(uint4*)&Asm[row * AS + c0] = p0;
            *(uint4*)&Asm[row * AS + c0 + 4] = p1;
        }
    }
    __syncthreads();

    // --- MMA phase ---
    float acc[NT][4];
#pragma unroll
    for (int nt = 0; nt < NT; nt++)
#pragma unroll
        for (int j = 0; j < 4; j++) acc[nt][j] = 0.f;

    for (int c = 0; c < K / KCB; c++) {
        int kc = c * KCB;
        for (int i = tid; i < KCB * (OUT / 4); i += 256) {
            int kk = i / (OUT / 4), j = i % (OUT / 4);
            float4 v = *(const float4*)&W[(size_t)(kc + kk) * OUT + 4 * j];
            uint4 t;
            t.x = f2tf32(v.x); t.y = f2tf32(v.y);
            t.z = f2tf32(v.z); t.w = f2tf32(v.w);
            *(uint4*)&Bsm[kk * BS + 4 * j] = t;
        }
        __syncthreads();
#pragma unroll
        for (int ksl = 0; ksl < KCB / 8; ksl++) {
            int k0 = kc + ksl * 8;
            uint32_t a[4];
            const uint32_t* ar0 = &Asm[(wid * 16 + g) * AS + k0 + t4];
            const uint32_t* ar1 = &Asm[(wid * 16 + g + 8) * AS + k0 + t4];
            a[0] = ar0[0]; a[1] = ar1[0]; a[2] = ar0[4]; a[3] = ar1[4];
            int kk0 = ksl * 8 + t4;
#pragma unroll
            for (int nt = 0; nt < NT; nt++) {
                uint32_t bb[2];
                bb[0] = Bsm[kk0 * BS + nt * 8 + g];
                bb[1] = Bsm[(kk0 + 4) * BS + nt * 8 + g];
                mma_tf32_16n8k8(acc[nt], a, bb);
            }
        }
        __syncthreads();
    }

    // epilogue: bias + relu -> g_buf2 fp32
    int node0 = tile0 + wid * 16 + g;
    int node1 = node0 + 8;
#pragma unroll
    for (int nt = 0; nt < NT; nt++) {
        int col = nt * 8 + 2 * t4;
        float2 bv = *(const float2*)&bias[col];
        float2 o0 = make_float2(fmaxf(acc[nt][0] + bv.x, 0.f),
                                fmaxf(acc[nt][1] + bv.y, 0.f));
        float2 o1 = make_float2(fmaxf(acc[nt][2] + bv.x, 0.f),
                                fmaxf(acc[nt][3] + bv.y, 0.f));
        if (node0 < NN) *(float2*)&g_buf2[(size_t)node0 * OUT + col] = o0;
        if (node1 < NN) *(float2*)&g_buf2[(size_t)node1 * OUT + col] = o1;
    }
}

// ---------------- tf32 mma.sync GEMM (layer 3: 128->96 -> fp16) --------------
template <int K, int OUT>
__global__ __launch_bounds__(256) void k_mmagemm(
        const float* __restrict__ hext, int hs,
        const float* __restrict__ W) {
    const float* __restrict__ h = sel_src(hext, hs);
    __half* __restrict__ hout = (__half*)g_hbuf;
    constexpr int KC = 32;
    constexpr int NCH = K / KC;
    constexpr int AS = 40;
    constexpr int BS = OUT + 8;
    constexpr int NT = OUT / 8;
    __shared__ uint32_t Asm[128 * AS];
    __shared__ uint32_t Bsm[KC * BS];

    int tid = threadIdx.x;
    int wid = tid >> 5, lane = tid & 31;
    int g = lane >> 2, t4 = lane & 3;
    int tile0 = blockIdx.x * 128;

    float acc[NT][4];
#pragma unroll
    for (int nt = 0; nt < NT; nt++)
#pragma unroll
        for (int j = 0; j < 4; j++) acc[nt][j] = 0.f;

    for (int c = 0; c < NCH; c++) {
        int kc = c * KC;
        for (int i = tid; i < 128 * (KC / 4); i += 256) {
            int row = i >> 3, j = i & 7;
            int node = tile0 + row;
            float4 v = make_float4(0.f, 0.f, 0.f, 0.f);
            if (node < NN) v = *(const float4*)&h[(size_t)node * K + kc + 4 * j];
            uint4 t;
            t.x = f2tf32(v.x); t.y = f2tf32(v.y);
            t.z = f2tf32(v.z); t.w = f2tf32(v.w);
            *(uint4*)&Asm[row * AS + 4 * j] = t;
        }
        for (int i = tid; i < KC * (OUT / 4); i += 256) {
            int k = i / (OUT / 4), j = i % (OUT / 4);
            float4 v = *(const float4*)&W[(size_t)(kc + k) * OUT + 4 * j];
            uint4 t;
            t.x = f2tf32(v.x); t.y = f2tf32(v.y);
            t.z = f2tf32(v.z); t.w = f2tf32(v.w);
            *(uint4*)&Bsm[k * BS + 4 * j] = t;
        }
        __syncthreads();
#pragma unroll
        for (int ks = 0; ks < KC / 8; ks++) {
            int k0 = ks * 8;
            uint32_t a[4];
            const uint32_t* ar0 = &Asm[(wid * 16 + g) * AS + k0 + t4];
            const uint32_t* ar1 = &Asm[(wid * 16 + g + 8) * AS + k0 + t4];
            a[0] = ar0[0]; a[1] = ar1[0]; a[2] = ar0[4]; a[3] = ar1[4];
#pragma unroll
            for (int nt = 0; nt < NT; nt++) {
                uint32_t bb[2];
                bb[0] = Bsm[(k0 + t4) * BS + nt * 8 + g];
                bb[1] = Bsm[(k0 + t4 + 4) * BS + nt * 8 + g];
                mma_tf32_16n8k8(acc[nt], a, bb);
            }
        }
        __syncthreads();
    }

    int node0 = tile0 + wid * 16 + g;
    int node1 = node0 + 8;
#pragma unroll
    for (int nt = 0; nt < NT; nt++) {
        int col = nt * 8 + 2 * t4;
        if (node0 < NN)
            *(__half2*)&hout[(size_t)node0 * OUT + col] =
                __floats2half2_rn(acc[nt][0], acc[nt][1]);
        if (node1 < NN)
            *(__half2*)&hout[(size_t)node1 * OUT + col] =
                __floats2half2_rn(acc[nt][2], acc[nt][3]);
    }
}

// ---------------- final aggregation: agg96 fp16-gather (+b3) -> out ----------
__global__ void k_agg96(float* __restrict__ out, const float* __restrict__ bias) {
    constexpr int CH = 96, GRP = 16, VEC = 8;
    const __half* __restrict__ hh = (const __half*)g_hbuf;
    int node = (blockIdx.x * blockDim.x + threadIdx.x) / GRP;
    int sub = threadIdx.x % GRP;
    if (node >= NN) return;
    bool act = sub < (CH / VEC);   // 12 of 16
    int c0 = sub * VEC;

    float acc[VEC];
#pragma unroll
    for (int v = 0; v < VEC; v++) acc[v] = 0.f;

    float sd = g_dinv[node];
    sd *= sd;
    if (act) {
        float f[VEC];
        ld_half8(hh + (size_t)node * CH + c0, f);
#pragma unroll
        for (int v = 0; v < VEC; v++) acc[v] = sd * f[v];
    }

    int e = g_rowptr[node];
    const int end = g_rowptr[node + 1];
    for (; e + 2 <= end; e += 2) {
        Edge e0 = g_edge[e];
        Edge e1 = g_edge[e + 1];
        if (act) {
            float f0[VEC], f1[VEC];
            ld_half8(hh + (size_t)e0.s * CH + c0, f0);
            ld_half8(hh + (size_t)e1.s * CH + c0, f1);
#pragma unroll
            for (int v = 0; v < VEC; v++)
                acc[v] += e0.w * f0[v] + e1.w * f1[v];
        }
    }
    if (e < end) {
        Edge e0 = g_edge[e];
        if (act) {
            float f0[VEC];
            ld_half8(hh + (size_t)e0.s * CH + c0, f0);
#pragma unroll
            for (int v = 0; v < VEC; v++) acc[v] += e0.w * f0[v];
        }
    }

    if (act) {
        float* orow = out + (size_t)node * CH + c0;
#pragma unroll
        for (int v = 0; v < VEC; v++) acc[v] += bias[c0 + v];
        *(float4*)&orow[0] = make_float4(acc[0], acc[1], acc[2], acc[3]);
        *(float4*)&orow[4] = make_float4(acc[4], acc[5], acc[6], acc[7]);
    }
}

// ---------------- launch ------------------------------------------------------
extern "C" void kernel_launch(void* const* d_in, const int* in_sizes, int n_in,
                              void* d_out, int out_size) {
    const float* x  = (const float*)d_in[0];
    const int* ei32 = (const int*)d_in[1];
    const float* W1 = (const float*)d_in[2];
    const float* b1 = (const float*)d_in[3];
    const float* W2 = (const float*)d_in[4];
    const float* b2 = (const float*)d_in[5];
    const float* W3 = (const float*)d_in[6];
    const float* b3 = (const float*)d_in[7];
    float* out      = (float*)d_out;
    int E = in_sizes[1] / 2;

    // 1) full CSR build in one kernel (grid barrier; NB blocks co-resident)
    k_build<<<NB, 256>>>(ei32, E);

    // 2) layer 1 fused: agg12(x) -> GEMM 12->64 (+b1, relu) -> fp16 hbuf
    k_aggemm1<<<(NN + 31) / 32, 128>>>(x, W1, b1);

    // 3) layer 2 fused: agg64(fp16) -> tf32 MMA 64->128 (+b2, relu) -> buf2
    k_aggemm2<<<(NN + 127) / 128, 256>>>(W2, b2);

    // 4) layer 3 GEMM: tf32 MMA 128->96 -> fp16 hbuf
    k_mmagemm<128, 96><<<(NN + 127) / 128, 256>>>(nullptr, 1, W3);

    // 5) final agg96 (+b3) -> out
    k_agg96<<<(NN * 16 + 255) / 256, 256>>>(out, b3);
}

// round 11
// speedup vs baseline: 1.2272x; 1.2272x over previous
#include <cuda_runtime.h>
#include <cuda_fp16.h>
#include <cstdint>

typedef unsigned long long ull;

constexpr int NN = 100000;   // nodes
constexpr int EE = 1600000;  // edges (no self loops)
constexpr int SCAN_NBLK = (NN + 1023) / 1024;  // 98

struct __align__(8) Edge { int s; float w; };

// ---------------- static device scratch --------------------------------------
__device__ int    g_is64;
__device__ int    g_cnt[NN];
__device__ int    g_rowptr[NN + 1];
__device__ int    g_bsum[128];
__device__ float  g_dinv[NN];
__device__ Edge   g_edge[EE];
__device__ float  g_fbuf[(size_t)NN * 12];    // fp32 agg12 output
__device__ __half g_hA[(size_t)NN * 128];     // fp16 ping
__device__ __half g_hB[(size_t)NN * 128];     // fp16 pong

// fp16 MMA m16n8k16 (arch-agnostic PTX, sm_80+), fp32 accumulate
__device__ __forceinline__ void mma_f16(float* c, uint32_t a0, uint32_t a1,
                                        uint32_t a2, uint32_t a3,
                                        uint32_t b0, uint32_t b1) {
    asm volatile(
        "mma.sync.aligned.m16n8k16.row.col.f32.f16.f16.f32 "
        "{%0,%1,%2,%3}, {%4,%5,%6,%7}, {%8,%9}, {%0,%1,%2,%3};"
        : "+f"(c[0]), "+f"(c[1]), "+f"(c[2]), "+f"(c[3])
        : "r"(a0), "r"(a1), "r"(a2), "r"(a3), "r"(b0), "r"(b1));
}

__device__ __forceinline__ uint32_t pack_h2(float a, float b) {
    __half2 h = __floats2half2_rn(a, b);
    return *(uint32_t*)&h;
}

// load 8 halfs (16B) -> 8 floats
__device__ __forceinline__ void ld_half8(const __half* p, float* f) {
    uint4 r = *(const uint4*)p;
    const __half2* h2 = (const __half2*)&r;
#pragma unroll
    for (int j = 0; j < 4; j++) {
        float2 t = __half22float2(h2[j]);
        f[2 * j] = t.x; f[2 * j + 1] = t.y;
    }
}

__device__ __forceinline__ int load_idx(const int* __restrict__ w, int pos, int is64) {
    if (is64) return ((const int2*)w)[pos].x;
    return w[pos];
}

// ---------------- CSR build (split kernels; R8-proven) ------------------------
__global__ void k_init(const int* __restrict__ w) {
    int i = blockIdx.x * blockDim.x + threadIdx.x;
    if (i < NN) g_cnt[i] = 0;
    if (blockIdx.x == 0 && threadIdx.x < 32) {
        int lane = threadIdx.x;
        int acc = 0;
        for (int j = lane; j < 1024; j += 32) acc |= w[2 * j + 1];
#pragma unroll
        for (int off = 16; off > 0; off >>= 1)
            acc |= __shfl_xor_sync(0xffffffffu, acc, off);
        if (lane == 0) g_is64 = (acc == 0) ? 1 : 0;
    }
}

__global__ void k_count(const int* __restrict__ w, int E) {
    int e0 = (blockIdx.x * blockDim.x + threadIdx.x) * 4;
    if (e0 >= E) return;
    int is64 = g_is64;
    int d[4];
    int nv = min(4, E - e0);
    if (is64) {
        if (nv == 4 && ((E + e0) & 1) == 0) {
            int4 a = *(const int4*)&w[2 * (E + e0)];
            int4 b = *(const int4*)&w[2 * (E + e0) + 4];
            d[0] = a.x; d[1] = a.z; d[2] = b.x; d[3] = b.z;
        } else {
            for (int j = 0; j < nv; j++) d[j] = ((const int2*)w)[E + e0 + j].x;
        }
    } else {
        if (nv == 4 && ((E + e0) & 3) == 0) {
            int4 a = *(const int4*)&w[E + e0];
            d[0] = a.x; d[1] = a.y; d[2] = a.z; d[3] = a.w;
        } else {
            for (int j = 0; j < nv; j++) d[j] = w[E + e0 + j];
        }
    }
    for (int j = 0; j < nv; j++)
        if ((unsigned)d[j] < (unsigned)NN) atomicAdd(&g_cnt[d[j]], 1);
}

__global__ void k_scan1() {
    __shared__ int s[256];
    int b = blockIdx.x, tid = threadIdx.x;
    int base = b * 1024 + tid * 4;
    int local = 0;
#pragma unroll
    for (int j = 0; j < 4; j++) {
        int i = base + j;
        if (i < NN) {
            int c = g_cnt[i];
            local += c;
            g_dinv[i] = rsqrtf((float)(c + 1));
        }
    }
    s[tid] = local;
    __syncthreads();
    for (int off = 128; off > 0; off >>= 1) {
        if (tid < off) s[tid] += s[tid + off];
        __syncthreads();
    }
    if (tid == 0) g_bsum[b] = s[0];
}

__global__ void k_scan2() {
    __shared__ int s[128];
    int tid = threadIdx.x;
    int v = (tid < SCAN_NBLK) ? g_bsum[tid] : 0;
    s[tid] = v;
    __syncthreads();
    for (int off = 1; off < 128; off <<= 1) {
        int t = (tid >= off) ? s[tid - off] : 0;
        __syncthreads();
        s[tid] += t;
        __syncthreads();
    }
    if (tid < SCAN_NBLK) g_bsum[tid] = s[tid] - v;
    if (tid == 127) g_rowptr[NN] = s[127];
}

__global__ void k_scan3() {
    __shared__ int s[256];
    int b = blockIdx.x, tid = threadIdx.x;
    int base = b * 1024 + tid * 4;
    int v[4];
#pragma unroll
    for (int j = 0; j < 4; j++) {
        int i = base + j;
        v[j] = (i < NN) ? g_cnt[i] : 0;
    }
    int local = v[0] + v[1] + v[2] + v[3];
    s[tid] = local;
    __syncthreads();
    for (int off = 1; off < 256; off <<= 1) {
        int t = (tid >= off) ? s[tid - off] : 0;
        __syncthreads();
        s[tid] += t;
        __syncthreads();
    }
    int excl = s[tid] - local + g_bsum[b];
#pragma unroll
    for (int j = 0; j < 4; j++) {
        int i = base + j;
        if (i < NN) { g_rowptr[i] = excl; g_cnt[i] = excl; }
        excl += v[j];
    }
}

__global__ void k_scatter(const int* __restrict__ w, int E) {
    int e0 = (blockIdx.x * blockDim.x + threadIdx.x) * 2;
    if (e0 >= E) return;
    int is64 = g_is64;
    int nv = min(2, E - e0);
    int s[2], d[2];
    if (is64) {
        if (nv == 2 && ((E + e0) & 1) == 0) {
            int4 a = *(const int4*)&w[2 * e0];
            int4 b = *(const int4*)&w[2 * (E + e0)];
            s[0] = a.x; s[1] = a.z; d[0] = b.x; d[1] = b.z;
        } else {
            for (int j = 0; j < nv; j++) {
                s[j] = ((const int2*)w)[e0 + j].x;
                d[j] = ((const int2*)w)[E + e0 + j].x;
            }
        }
    } else {
        if (nv == 2 && ((E + e0) & 1) == 0) {
            int2 a = *(const int2*)&w[e0];
            int2 b = *(const int2*)&w[E + e0];
            s[0] = a.x; s[1] = a.y; d[0] = b.x; d[1] = b.y;
        } else {
            for (int j = 0; j < nv; j++) { s[j] = w[e0 + j]; d[j] = w[E + e0 + j]; }
        }
    }
    for (int j = 0; j < nv; j++) {
        if ((unsigned)s[j] < (unsigned)NN && (unsigned)d[j] < (unsigned)NN) {
            int pos = atomicAdd(&g_cnt[d[j]], 1);
            Edge ed; ed.s = s[j]; ed.w = g_dinv[s[j]] * g_dinv[d[j]];
            g_edge[pos] = ed;
        }
    }
}

// ---------------- agg12: fp32 gather from x -> g_fbuf ------------------------
__global__ void k_agg12(const float* __restrict__ x) {
    constexpr int CH = 12, GRP = 16;
    int node = (blockIdx.x * blockDim.x + threadIdx.x) / GRP;
    int sub = threadIdx.x % GRP;
    if (node >= NN) return;
    bool act = sub < CH;
    float acc = 0.f;
    float sd = g_dinv[node];
    sd *= sd;
    if (act) acc = sd * x[(size_t)node * CH + sub];
    int e = g_rowptr[node];
    const int end = g_rowptr[node + 1];
    for (; e + 2 <= end; e += 2) {
        Edge e0 = g_edge[e];
        Edge e1 = g_edge[e + 1];
        if (act)
            acc += e0.w * x[(size_t)e0.s * CH + sub] + e1.w * x[(size_t)e1.s * CH + sub];
    }
    if (e < end) {
        Edge e0 = g_edge[e];
        if (act) acc += e0.w * x[(size_t)e0.s * CH + sub];
    }
    if (act) g_fbuf[(size_t)node * CH + sub] = acc;
}

// ---------------- GEMM1 scalar: g_fbuf 12 -> 64 (+b1, relu) -> g_hA fp16 -----
__global__ __launch_bounds__(128) void k_gemm1(const float* __restrict__ W,
                                               const float* __restrict__ bias) {
    constexpr int IN = 12, OUT = 64, BN = 32, HS = BN + 4;
    __shared__ float Wsm[IN * OUT];
    __shared__ float Hsm[IN * HS];
    int tid = threadIdx.x;
    int n0blk = blockIdx.x * BN;

    for (int i = tid; i < IN * OUT; i += 128) Wsm[i] = W[i];
    for (int i = tid; i < BN * IN; i += 128) {
        int n = i / IN, k = i % IN;
        int node = n0blk + n;
        Hsm[k * HS + n] = (node < NN) ? g_fbuf[(size_t)node * IN + k] : 0.f;
    }
    __syncthreads();

    int tx = tid & 15, ty = tid >> 4;
    int c0 = tx * 4, n0 = ty * 4;
    float acc[4][4];
#pragma unroll
    for (int a = 0; a < 4; a++)
#pragma unroll
        for (int c = 0; c < 4; c++) acc[a][c] = 0.f;
#pragma unroll
    for (int k = 0; k < IN; k++) {
        float4 hv4 = *(const float4*)&Hsm[k * HS + n0];
        float4 wv4 = *(const float4*)&Wsm[k * OUT + c0];
        float hv[4] = {hv4.x, hv4.y, hv4.z, hv4.w};
        float wv[4] = {wv4.x, wv4.y, wv4.z, wv4.w};
#pragma unroll
        for (int a = 0; a < 4; a++)
#pragma unroll
            for (int c = 0; c < 4; c++) acc[a][c] += hv[a] * wv[c];
    }
    float4 b4 = *(const float4*)&bias[c0];
#pragma unroll
    for (int a = 0; a < 4; a++) {
        int node = n0blk + n0 + a;
        if (node < NN) {
            float t0 = fmaxf(acc[a][0] + b4.x, 0.f);
            float t1 = fmaxf(acc[a][1] + b4.y, 0.f);
            float t2 = fmaxf(acc[a][2] + b4.z, 0.f);
            float t3 = fmaxf(acc[a][3] + b4.w, 0.f);
            *(__half2*)&g_hA[(size_t)node * OUT + c0] = __floats2half2_rn(t0, t1);
            *(__half2*)&g_hA[(size_t)node * OUT + c0 + 2] = __floats2half2_rn(t2, t3);
        }
    }
}

// ---------------- agg64: fp16 gather g_hA -> fp16 g_hB (fp32 accum) ----------
__global__ void k_agg64() {
    constexpr int CH = 64, GRP = 8, VEC = 8;
    const __half* __restrict__ hh = g_hA;
    int node = (blockIdx.x * blockDim.x + threadIdx.x) / GRP;
    int sub = threadIdx.x % GRP;
    if (node >= NN) return;
    int c0 = sub * VEC;

    float acc[VEC];
    float sd = g_dinv[node];
    sd *= sd;
    {
        float f[VEC];
        ld_half8(hh + (size_t)node * CH + c0, f);
#pragma unroll
        for (int v = 0; v < VEC; v++) acc[v] = sd * f[v];
    }
    int e = g_rowptr[node];
    const int end = g_rowptr[node + 1];
    for (; e + 2 <= end; e += 2) {
        Edge e0 = g_edge[e];
        Edge e1 = g_edge[e + 1];
        float f0[VEC], f1[VEC];
        ld_half8(hh + (size_t)e0.s * CH + c0, f0);
        ld_half8(hh + (size_t)e1.s * CH + c0, f1);
#pragma unroll
        for (int v = 0; v < VEC; v++) acc[v] += e0.w * f0[v] + e1.w * f1[v];
    }
    if (e < end) {
        Edge e0 = g_edge[e];
        float f0[VEC];
        ld_half8(hh + (size_t)e0.s * CH + c0, f0);
#pragma unroll
        for (int v = 0; v < VEC; v++) acc[v] += e0.w * f0[v];
    }
    uint4 o;
    o.x = pack_h2(acc[0], acc[1]); o.y = pack_h2(acc[2], acc[3]);
    o.z = pack_h2(acc[4], acc[5]); o.w = pack_h2(acc[6], acc[7]);
    *(uint4*)&g_hB[(size_t)node * CH + c0] = o;
}

// ---------------- fp16 MMA GEMM: src fp16 [128,K] @ W[K,OUT] -----------------
// SRC_A/DST_A select g_hA/g_hB. K chunked at 64 halfs. m16n8k16 fragments.
template <int K, int OUT, bool SRC_A, bool DST_A, bool BIAS, bool RELU>
__global__ __launch_bounds__(256) void k_hgemm(const float* __restrict__ W,
                                               const float* __restrict__ bias) {
    const __half* __restrict__ src = SRC_A ? (const __half*)g_hA : (const __half*)g_hB;
    __half* __restrict__ dst = DST_A ? (__half*)g_hA : (__half*)g_hB;
    constexpr int KC = 64;                 // halfs per chunk
    constexpr int NCH = K / KC;
    constexpr int AS = 36;                 // b32 stride: 32 data + 4 pad (4g+t4 banks)
    constexpr int BS = 36;
    constexpr int NT = OUT / 8;
    __shared__ uint32_t Asm[128 * AS];     // 18.4KB
    __shared__ uint32_t Bsm[OUT * BS];     // 18.4/13.8KB

    int tid = threadIdx.x;
    int wid = tid >> 5, lane = tid & 31;
    int g = lane >> 2, t4 = lane & 3;
    int tile0 = blockIdx.x * 128;

    float acc[NT][4];
#pragma unroll
    for (int nt = 0; nt < NT; nt++)
#pragma unroll
        for (int j = 0; j < 4; j++) acc[nt][j] = 0.f;

    for (int c = 0; c < NCH; c++) {
        int kc = c * KC;
        // stage A: 128 rows x 64 halfs = 8 uint4 per row
        for (int i = tid; i < 128 * 8; i += 256) {
            int row = i >> 3, j = i & 7;
            int node = tile0 + row;
            uint4 v = make_uint4(0u, 0u, 0u, 0u);
            if (node < NN) v = *(const uint4*)&src[(size_t)node * K + kc + 8 * j];
            *(uint4*)&Asm[row * AS + 4 * j] = v;
        }
        // stage B: OUT cols x 32 b32 (col-major K-contiguous), fp32 W -> fp16
        for (int i = tid; i < OUT * 32; i += 256) {
            int col = i % OUT, kk = i / OUT;
            float w0 = W[(size_t)(kc + 2 * kk) * OUT + col];
            float w1 = W[(size_t)(kc + 2 * kk + 1) * OUT + col];
            Bsm[col * BS + kk] = pack_h2(w0, w1);
        }
        __syncthreads();

#pragma unroll
        for (int ks = 0; ks < KC / 16; ks++) {
            int ko = ks * 8;   // b32 offset of this k16 step
            const uint32_t* ar0 = &Asm[(wid * 16 + g) * AS + ko + t4];
            const uint32_t* ar1 = &Asm[(wid * 16 + g + 8) * AS + ko + t4];
            uint32_t a0 = ar0[0], a1 = ar1[0], a2 = ar0[4], a3 = ar1[4];
#pragma unroll
            for (int nt = 0; nt < NT; nt++) {
                uint32_t b0 = Bsm[(nt * 8 + g) * BS + ko + t4];
                uint32_t b1 = Bsm[(nt * 8 + g) * BS + ko + t4 + 4];
                mma_f16(acc[nt], a0, a1, a2, a3, b0, b1);
            }
        }
        __syncthreads();
    }

    int node0 = tile0 + wid * 16 + g;
    int node1 = node0 + 8;
#pragma unroll
    for (int nt = 0; nt < NT; nt++) {
        int col = nt * 8 + 2 * t4;
        float2 bv = make_float2(0.f, 0.f);
        if (BIAS) bv = *(const float2*)&bias[col];
        float o0x = acc[nt][0] + bv.x, o0y = acc[nt][1] + bv.y;
        float o1x = acc[nt][2] + bv.x, o1y = acc[nt][3] + bv.y;
        if (RELU) {
            o0x = fmaxf(o0x, 0.f); o0y = fmaxf(o0y, 0.f);
            o1x = fmaxf(o1x, 0.f); o1y = fmaxf(o1y, 0.f);
        }
        if (node0 < NN)
            *(__half2*)&dst[(size_t)node0 * OUT + col] = __floats2half2_rn(o0x, o0y);
        if (node1 < NN)
            *(__half2*)&dst[(size_t)node1 * OUT + col] = __floats2half2_rn(o1x, o1y);
    }
}

// ---------------- agg96: fp16 gather g_hB (+b3) -> fp32 out ------------------
__global__ void k_agg96(float* __restrict__ out, const float* __restrict__ bias) {
    constexpr int CH = 96, GRP = 16, VEC = 8;
    const __half* __restrict__ hh = g_hB;
    int node = (blockIdx.x * blockDim.x + threadIdx.x) / GRP;
    int sub = threadIdx.x % GRP;
    if (node >= NN) return;
    bool act = sub < (CH / VEC);   // 12 of 16
    int c0 = sub * VEC;

    float acc[VEC];
#pragma unroll
    for (int v = 0; v < VEC; v++) acc[v] = 0.f;

    float sd = g_dinv[node];
    sd *= sd;
    if (act) {
        float f[VEC];
        ld_half8(hh + (size_t)node * CH + c0, f);
#pragma unroll
        for (int v = 0; v < VEC; v++) acc[v] = sd * f[v];
    }
    int e = g_rowptr[node];
    const int end = g_rowptr[node + 1];
    for (; e + 2 <= end; e += 2) {
        Edge e0 = g_edge[e];
        Edge e1 = g_edge[e + 1];
        if (act) {
            float f0[VEC], f1[VEC];
            ld_half8(hh + (size_t)e0.s * CH + c0, f0);
            ld_half8(hh + (size_t)e1.s * CH + c0, f1);
#pragma unroll
            for (int v = 0; v < VEC; v++) acc[v] += e0.w * f0[v] + e1.w * f1[v];
        }
    }
    if (e < end) {
        Edge e0 = g_edge[e];
        if (act) {
            float f0[VEC];
            ld_half8(hh + (size_t)e0.s * CH + c0, f0);
#pragma unroll
            for (int v = 0; v < VEC; v++) acc[v] += e0.w * f0[v];
        }
    }
    if (act) {
        float* orow = out + (size_t)node * CH + c0;
#pragma unroll
        for (int v = 0; v < VEC; v++) acc[v] += bias[c0 + v];
        *(float4*)&orow[0] = make_float4(acc[0], acc[1], acc[2], acc[3]);
        *(float4*)&orow[4] = make_float4(acc[4], acc[5], acc[6], acc[7]);
    }
}

// ---------------- launch ------------------------------------------------------
extern "C" void kernel_launch(void* const* d_in, const int* in_sizes, int n_in,
                              void* d_out, int out_size) {
    const float* x  = (const float*)d_in[0];
    const int* ei32 = (const int*)d_in[1];
    const float* W1 = (const float*)d_in[2];
    const float* b1 = (const float*)d_in[3];
    const float* W2 = (const float*)d_in[4];
    const float* b2 = (const float*)d_in[5];
    const float* W3 = (const float*)d_in[6];
    const float* b3 = (const float*)d_in[7];
    float* out      = (float*)d_out;
    int E = in_sizes[1] / 2;

    // CSR build (split, full-occupancy)
    k_init<<<(NN + 255) / 256, 256>>>(ei32);
    k_count<<<(E / 4 + 255) / 256, 256>>>(ei32, E);
    k_scan1<<<SCAN_NBLK, 256>>>();
    k_scan2<<<1, 128>>>();
    k_scan3<<<SCAN_NBLK, 256>>>();
    k_scatter<<<(E / 2 + 255) / 256, 256>>>(ei32, E);

    int gMMA = (NN + 127) / 128;  // 782

    // layer 1: agg12(x) -> fbuf -> scalar GEMM 12->64 (+b1, relu) -> hA fp16
    k_agg12<<<(NN * 16 + 255) / 256, 256>>>(x);
    k_gemm1<<<(NN + 31) / 32, 128>>>(W1, b1);

    // layer 2: agg64 hA->hB fp16 -> f16 MMA 64->128 (+b2, relu) -> hA fp16
    k_agg64<<<(NN * 8 + 255) / 256, 256>>>();
    k_hgemm<64, 128, false, true, true, true><<<gMMA, 256>>>(W2, b2);

    // layer 3: f16 MMA 128->96 hA -> hB fp16 -> agg96 (+b3) -> out fp32
    k_hgemm<128, 96, true, false, false, false><<<gMMA, 256>>>(W3, nullptr);
    k_agg96<<<(NN * 16 + 255) / 256, 256>>>(out, b3);
}